// round 1
// baseline (speedup 1.0000x reference)
#include <cuda_runtime.h>
#include <math.h>

// ---------------- problem constants ----------------
#define BSZ   4096
#define DIM   128
#define KNBR  64
#define NREL  16
#define KAGG  2048          // NREL * DIM
#define KCAT  2176          // KAGG + DIM
#define NQKV  384

// ---------------- device scratch (static, no allocation) ----------------
__device__ float g_agg [BSZ * KAGG];          // [B, R*D]
__device__ float g_x   [3][BSZ * DIM];        // x0, x1, x2
__device__ float g_qkv [2][BSZ * NQKV];       // qkv for layer outputs 1 and 2
__device__ float g_obar[BSZ * DIM];           // mean attention output before out_proj
__device__ float g_Wcat[2][KCAT * DIM];       // per-layer packed [W_rel_flat ; res_W^T]
__device__ float g_inT [DIM * NQKV];          // in_proj_w transposed  [d][e3]
__device__ float g_outT[DIM * DIM];           // out_proj_w transposed [d][e]

// ---------------- prep: pack / transpose weights ----------------
// total elements: 2*2176*128 (Wcat) + 128*384 (inT) + 128*128 (outT) = 622592
__global__ void prep_kernel(const float* __restrict__ Wrel,
                            const float* __restrict__ resW,
                            const float* __restrict__ inW,
                            const float* __restrict__ outW)
{
    int i = blockIdx.x * 256 + threadIdx.x;
    const int NW = 2 * KCAT * DIM;
    const int NI = DIM * NQKV;
    if (i < NW) {
        int l   = i / (KCAT * DIM);
        int rem = i - l * (KCAT * DIM);
        int j   = rem >> 7;         // 0..2175
        int e   = rem & 127;
        float v;
        if (j < KAGG) {
            // W_rel[l, r, d, e], j = r*128+d  -> flat (l*2048 + j)*128 + e
            v = Wrel[(l * KAGG + j) * DIM + e];
        } else {
            // res_W[l, e, d] transposed
            int d = j - KAGG;
            v = resW[(l * DIM + e) * DIM + d];
        }
        g_Wcat[0][i] = v;  // flat write across both layers
    } else if (i < NW + NI) {
        int t  = i - NW;
        int d  = t / NQKV;
        int e3 = t - d * NQKV;
        g_inT[t] = inW[e3 * DIM + d];
    } else if (i < NW + NI + DIM * DIM) {
        int t = i - NW - NI;
        int d = t >> 7;
        int e = t & 127;
        g_outT[t] = outW[e * DIM + d];
    }
}

// ---------------- agg: per-row relation scatter + x0 gather ----------------
__global__ void __launch_bounds__(128)
agg_kernel(const int* __restrict__ drug,
           const int* __restrict__ adjE,
           const int* __restrict__ adjR,
           const float* __restrict__ ew,
           const float* __restrict__ E)
{
    __shared__ float s[NREL * DIM];
    __shared__ int   se[KNBR];
    __shared__ int   sr[KNBR];
    __shared__ float sw[KNBR];

    const int b = blockIdx.x;
    const int d = threadIdx.x;

    #pragma unroll
    for (int r = 0; r < NREL; r++) s[r * DIM + d] = 0.f;

    if (d < KNBR) {
        se[d] = adjE[b * KNBR + d];
        sr[d] = adjR[b * KNBR + d];
        sw[d] = ew  [b * KNBR + d];
    }
    // gather x0 = E[drug[b]]
    g_x[0][b * DIM + d] = E[drug[b] * DIM + d];
    __syncthreads();

    #pragma unroll 1
    for (int k = 0; k < KNBR; k += 4) {
        float e0 = E[se[k + 0] * DIM + d];
        float e1 = E[se[k + 1] * DIM + d];
        float e2 = E[se[k + 2] * DIM + d];
        float e3 = E[se[k + 3] * DIM + d];
        s[sr[k + 0] * DIM + d] += sw[k + 0] * e0;
        s[sr[k + 1] * DIM + d] += sw[k + 1] * e1;
        s[sr[k + 2] * DIM + d] += sw[k + 2] * e2;
        s[sr[k + 3] * DIM + d] += sw[k + 3] * e3;
    }
    // thread d owns column d for every r: no barrier needed
    float* ao = g_agg + b * KAGG;
    #pragma unroll
    for (int r = 0; r < NREL; r++) ao[r * DIM + d] = s[r * DIM + d];
}

// ---------------- generic fused GEMM ----------------
// C[b, e] = epilogue( sum_j A[b,j] * Bm[j,e] )
// A is logically [B, K1+K2]: first K1 cols from A1 (row stride K1),
// last K2 cols from A2 (row stride K2).  Bm is row-major [(K1+K2) x Ntot].
// epilogue: + bias[e]  (+ addsrc[b*Ntot+e])  (relu)
// BM=32, BN=128, BK=32, 256 threads, 4x4 per-thread microtile.
__global__ void __launch_bounds__(256)
gemm_fused(const float* __restrict__ A1, int K1,
           const float* __restrict__ A2, int K2,
           const float* __restrict__ Bm,
           const float* __restrict__ bias,
           const float* __restrict__ addsrc,
           float* __restrict__ Cout,
           int Ntot, int doRelu)
{
    __shared__ __align__(16) float As[32][32];
    __shared__ __align__(16) float Bs[32][128];

    const int tid = threadIdx.x;
    const int bm  = blockIdx.x * 32;
    const int bn  = blockIdx.y * 128;
    const int Kdim = K1 + K2;

    const int r0 = (tid >> 5) << 2;     // warp id * 4   (output rows)
    const int c0 = (tid & 31) << 2;     // lane * 4      (output cols)

    const int arow  = tid >> 3;         // 0..31
    const int acol  = (tid & 7) << 2;   // 0..28 step 4
    const int bcol  = (tid & 31) << 2;  // 0..124 step 4
    const int brow0 = tid >> 5;         // 0..7

    float acc[4][4];
    #pragma unroll
    for (int i = 0; i < 4; i++)
        #pragma unroll
        for (int j = 0; j < 4; j++) acc[i][j] = 0.f;

    for (int k0 = 0; k0 < Kdim; k0 += 32) {
        // A tile (segment select per k-tile; 32 | K1 so no straddle)
        const float* ap;
        if (k0 < K1) ap = A1 + (bm + arow) * K1 + k0 + acol;
        else         ap = A2 + (bm + arow) * K2 + (k0 - K1) + acol;
        float4 av = *(const float4*)ap;
        *(float4*)&As[arow][acol] = av;

        // B tile: 4 float4 rows per thread
        #pragma unroll
        for (int i = 0; i < 4; i++) {
            int kk = brow0 + i * 8;
            float4 bv = *(const float4*)(Bm + (k0 + kk) * Ntot + bn + bcol);
            *(float4*)&Bs[kk][bcol] = bv;
        }
        __syncthreads();

        #pragma unroll
        for (int kk = 0; kk < 32; kk++) {
            float a0 = As[r0 + 0][kk];
            float a1 = As[r0 + 1][kk];
            float a2 = As[r0 + 2][kk];
            float a3 = As[r0 + 3][kk];
            float4 bv = *(const float4*)&Bs[kk][c0];
            acc[0][0] += a0 * bv.x; acc[0][1] += a0 * bv.y; acc[0][2] += a0 * bv.z; acc[0][3] += a0 * bv.w;
            acc[1][0] += a1 * bv.x; acc[1][1] += a1 * bv.y; acc[1][2] += a1 * bv.z; acc[1][3] += a1 * bv.w;
            acc[2][0] += a2 * bv.x; acc[2][1] += a2 * bv.y; acc[2][2] += a2 * bv.z; acc[2][3] += a2 * bv.w;
            acc[3][0] += a3 * bv.x; acc[3][1] += a3 * bv.y; acc[3][2] += a3 * bv.z; acc[3][3] += a3 * bv.w;
        }
        __syncthreads();
    }

    #pragma unroll
    for (int i = 0; i < 4; i++) {
        int gr = bm + r0 + i;
        #pragma unroll
        for (int j = 0; j < 4; j++) {
            int gc = bn + c0 + j;
            float v = acc[i][j];
            if (bias)   v += bias[gc];
            if (addsrc) v += addsrc[gr * Ntot + gc];
            if (doRelu) v = fmaxf(v, 0.f);
            Cout[gr * Ntot + gc] = v;
        }
    }
}

// ---------------- attention (L=2, one warp per head) ----------------
__global__ void __launch_bounds__(128)
attn_kernel()
{
    const int b = blockIdx.x;
    const int h = threadIdx.x >> 5;
    const int d = threadIdx.x & 31;

    const float* p0 = g_qkv[0] + b * NQKV + h * 32 + d;  // layer output 1
    const float* p1 = g_qkv[1] + b * NQKV + h * 32 + d;  // layer output 2
    float q0 = p0[0], k0 = p0[128], v0 = p0[256];
    float q1 = p1[0], k1 = p1[128], v1 = p1[256];

    float s00 = q0 * k0, s01 = q0 * k1, s10 = q1 * k0, s11 = q1 * k1;
    #pragma unroll
    for (int o = 16; o; o >>= 1) {
        s00 += __shfl_xor_sync(0xffffffffu, s00, o);
        s01 += __shfl_xor_sync(0xffffffffu, s01, o);
        s10 += __shfl_xor_sync(0xffffffffu, s10, o);
        s11 += __shfl_xor_sync(0xffffffffu, s11, o);
    }
    const float inv = 0.17677669529663687f;  // 1/sqrt(32)
    s00 *= inv; s01 *= inv; s10 *= inv; s11 *= inv;

    float m0 = fmaxf(s00, s01), m1 = fmaxf(s10, s11);
    float e00 = expf(s00 - m0), e01 = expf(s01 - m0);
    float e10 = expf(s10 - m1), e11 = expf(s11 - m1);
    float o0 = (e00 * v0 + e01 * v1) / (e00 + e01);
    float o1 = (e10 * v0 + e11 * v1) / (e10 + e11);

    g_obar[b * DIM + h * 32 + d] = 0.5f * (o0 + o1);
}

// ---------------- host launcher ----------------
extern "C" void kernel_launch(void* const* d_in, const int* in_sizes, int n_in,
                              void* d_out, int out_size)
{
    const int*   drug = (const int*)  d_in[0];
    const int*   adjE = (const int*)  d_in[1];
    const int*   adjR = (const int*)  d_in[2];
    const float* ew   = (const float*)d_in[3];
    const float* E    = (const float*)d_in[4];
    const float* Wrel = (const float*)d_in[5];
    const float* resW = (const float*)d_in[6];
    const float* resb = (const float*)d_in[7];
    const float* inW  = (const float*)d_in[8];
    const float* inB  = (const float*)d_in[9];
    const float* outW = (const float*)d_in[10];
    const float* outB = (const float*)d_in[11];

    float *agg, *xbuf, *qkv, *obar, *Wcat, *inT, *outT;
    cudaGetSymbolAddress((void**)&agg,  g_agg);
    cudaGetSymbolAddress((void**)&xbuf, g_x);
    cudaGetSymbolAddress((void**)&qkv,  g_qkv);
    cudaGetSymbolAddress((void**)&obar, g_obar);
    cudaGetSymbolAddress((void**)&Wcat, g_Wcat);
    cudaGetSymbolAddress((void**)&inT,  g_inT);
    cudaGetSymbolAddress((void**)&outT, g_outT);

    float* x0 = xbuf;
    float* x1 = xbuf + BSZ * DIM;
    float* x2 = xbuf + 2 * BSZ * DIM;

    // 1. weight pack/transpose (622592 elems)
    prep_kernel<<<2432, 256>>>(Wrel, resW, inW, outW);

    // 2. relation scatter + x0 gather
    agg_kernel<<<BSZ, 128>>>(drug, adjE, adjR, ew, E);

    // 3. layer 0: x1 = relu(x0 + agg@W0 + x0@R0^T + b0)
    gemm_fused<<<dim3(BSZ / 32, 1), 256>>>(
        agg, KAGG, x0, DIM, Wcat, resb, x0, x1, DIM, 1);

    // 4. layer 1: x2 = relu(x1 + agg@W1 + x1@R1^T + b1)
    gemm_fused<<<dim3(BSZ / 32, 1), 256>>>(
        agg, KAGG, x1, DIM, Wcat + KCAT * DIM, resb + DIM, x1, x2, DIM, 1);

    // 5. qkv projections for both layer outputs
    gemm_fused<<<dim3(BSZ / 32, 3), 256>>>(
        x1, DIM, nullptr, 0, inT, inB, nullptr, qkv, NQKV, 0);
    gemm_fused<<<dim3(BSZ / 32, 3), 256>>>(
        x2, DIM, nullptr, 0, inT, inB, nullptr, qkv + BSZ * NQKV, NQKV, 0);

    // 6. attention over the 2-token sequence, averaged over L
    attn_kernel<<<BSZ, 128>>>();

    // 7. out projection -> d_out
    gemm_fused<<<dim3(BSZ / 32, 1), 256>>>(
        obar, DIM, nullptr, 0, outT, outB, nullptr, (float*)d_out, DIM, 0);
}

// round 2
// speedup vs baseline: 1.3989x; 1.3989x over previous
#include <cuda_runtime.h>
#include <math.h>

typedef unsigned long long u64;

// ---------------- problem constants ----------------
#define BSZ   4096
#define DIM   128
#define KNBR  64
#define NREL  16
#define KAGG  2048          // NREL * DIM
#define KCAT  2176          // KAGG + DIM
#define NQKV  384
#define NSPLIT 4
#define KCHUNK 544          // KCAT / NSPLIT (17 k-tiles of 32)

// ---------------- device scratch (static, no allocation) ----------------
__device__ float g_agg [BSZ * KAGG];          // [B, R*D]
__device__ float g_x   [3][BSZ * DIM];        // x0, x1, x2 (x1,x2 contiguous)
__device__ float g_qkv [2][BSZ * NQKV];       // qkv for both layer outputs
__device__ float g_obar[BSZ * DIM];           // mean attn output before out_proj
__device__ float g_Wcat[2][KCAT * DIM];       // packed [W_rel_flat ; res_W^T] per layer
__device__ float g_inT [DIM * NQKV];          // in_proj_w transposed  [d][e3]
__device__ float g_outT[DIM * DIM];           // out_proj_w transposed [d][e]
__device__ float g_part[NSPLIT * BSZ * DIM];  // split-K partials

// ---------------- f32x2 helpers (Blackwell packed fp32 FMA) ----------------
__device__ __forceinline__ u64 pack2(float x) {
    u64 r; asm("mov.b64 %0, {%1,%1};" : "=l"(r) : "f"(x)); return r;
}
__device__ __forceinline__ void ffma2(u64& d, u64 a, u64 b) {
    asm("fma.rn.f32x2 %0, %1, %2, %0;" : "+l"(d) : "l"(a), "l"(b));
}
__device__ __forceinline__ void unpack2(u64 v, float& lo, float& hi) {
    asm("mov.b64 {%0,%1}, %2;" : "=f"(lo), "=f"(hi) : "l"(v));
}

// ---------------- prep: pack / transpose weights ----------------
__global__ void prep_kernel(const float* __restrict__ Wrel,
                            const float* __restrict__ resW,
                            const float* __restrict__ inW,
                            const float* __restrict__ outW)
{
    int i = blockIdx.x * 256 + threadIdx.x;
    const int NW = 2 * KCAT * DIM;
    const int NI = DIM * NQKV;
    if (i < NW) {
        int l   = i / (KCAT * DIM);
        int rem = i - l * (KCAT * DIM);
        int j   = rem >> 7;
        int e   = rem & 127;
        float v;
        if (j < KAGG) v = Wrel[(l * KAGG + j) * DIM + e];
        else          v = resW[(l * DIM + e) * DIM + (j - KAGG)];
        g_Wcat[0][i] = v;
    } else if (i < NW + NI) {
        int t  = i - NW;
        int d  = t / NQKV;
        int e3 = t - d * NQKV;
        g_inT[t] = inW[e3 * DIM + d];
    } else if (i < NW + NI + DIM * DIM) {
        int t = i - NW - NI;
        g_outT[t] = outW[(t & 127) * DIM + (t >> 7)];
    }
}

// ---------------- agg: per-row relation scatter + x0 gather ----------------
__global__ void __launch_bounds__(128)
agg_kernel(const int* __restrict__ drug,
           const int* __restrict__ adjE,
           const int* __restrict__ adjR,
           const float* __restrict__ ew,
           const float* __restrict__ E)
{
    __shared__ float s[NREL * DIM];
    __shared__ int   se[KNBR];
    __shared__ int   sr[KNBR];
    __shared__ float sw[KNBR];

    const int b = blockIdx.x;
    const int d = threadIdx.x;

    #pragma unroll
    for (int r = 0; r < NREL; r++) s[r * DIM + d] = 0.f;

    if (d < KNBR) {
        se[d] = adjE[b * KNBR + d];
        sr[d] = adjR[b * KNBR + d];
        sw[d] = ew  [b * KNBR + d];
    }
    g_x[0][b * DIM + d] = E[(long)drug[b] * DIM + d];
    __syncthreads();

    #pragma unroll 1
    for (int k = 0; k < KNBR; k += 4) {
        float e0 = E[(long)se[k + 0] * DIM + d];
        float e1 = E[(long)se[k + 1] * DIM + d];
        float e2 = E[(long)se[k + 2] * DIM + d];
        float e3 = E[(long)se[k + 3] * DIM + d];
        s[sr[k + 0] * DIM + d] += sw[k + 0] * e0;
        s[sr[k + 1] * DIM + d] += sw[k + 1] * e1;
        s[sr[k + 2] * DIM + d] += sw[k + 2] * e2;
        s[sr[k + 3] * DIM + d] += sw[k + 3] * e3;
    }
    float* ao = g_agg + (long)b * KAGG;
    #pragma unroll
    for (int r = 0; r < NREL; r++) ao[r * DIM + d] = s[r * DIM + d];
}

// ---------------- 128x128x32 GEMM, 8x8 microtile, packed f32x2 FMA ----------
// C[b,e] = sum_j A[b,j] * Bm[j,e]   over k in [z*kchunk, (z+1)*kchunk)
// A logically [M, K1+K2]: cols <K1 from A1 (stride K1), rest from A2 (stride K2).
// gridDim.z>1: writes raw partial at C + z*partStride. bias!=0: adds bias[e].
__global__ void __launch_bounds__(256, 1)
gemm128(const float* __restrict__ A1, int K1,
        const float* __restrict__ A2, int K2,
        const float* __restrict__ Bm, int Ntot,
        float* __restrict__ C, long partStride,
        int kchunk, const float* __restrict__ bias)
{
    __shared__ __align__(16) float As[32][128];   // As[kk][row]
    __shared__ __align__(16) float Bs[32][128];   // Bs[kk][col]

    const int tid  = threadIdx.x;
    const int bm   = blockIdx.x * 128;
    const int bn   = blockIdx.y * 128;
    const int kbeg = blockIdx.z * kchunk;
    const int ntile = kchunk >> 5;

    // global->smem mapping
    const int arow = tid >> 1;            // 0..127
    const int acol = (tid & 1) * 16;      // 0 or 16
    const int bkk  = tid >> 3;            // 0..31
    const int bcol = (tid & 7) * 4;       // 0..28

    // compute mapping
    const int ty = tid >> 4, tx = tid & 15;
    const int r0 = ty * 8, c0 = tx * 8;

    u64 acc[4][8];
    #pragma unroll
    for (int i = 0; i < 4; i++)
        #pragma unroll
        for (int j = 0; j < 8; j++) acc[i][j] = 0ull;

    float4 aR[4], bR[4];

    // prefetch tile 0
    {
        int k0 = kbeg;
        const float* ap = (k0 < K1)
            ? A1 + (long)(bm + arow) * K1 + k0 + acol
            : A2 + (long)(bm + arow) * K2 + (k0 - K1) + acol;
        #pragma unroll
        for (int i = 0; i < 4; i++) aR[i] = *(const float4*)(ap + i * 4);
        const float* bp = Bm + (long)(k0 + bkk) * Ntot + bn + bcol;
        #pragma unroll
        for (int i = 0; i < 4; i++) bR[i] = *(const float4*)(bp + i * 32);
    }

    for (int t = 0; t < ntile; t++) {
        __syncthreads();
        #pragma unroll
        for (int i = 0; i < 4; i++) {
            As[acol + i * 4 + 0][arow] = aR[i].x;
            As[acol + i * 4 + 1][arow] = aR[i].y;
            As[acol + i * 4 + 2][arow] = aR[i].z;
            As[acol + i * 4 + 3][arow] = aR[i].w;
            *(float4*)&Bs[bkk][bcol + i * 32] = bR[i];
        }
        __syncthreads();

        if (t + 1 < ntile) {
            int k0 = kbeg + (t + 1) * 32;
            const float* ap = (k0 < K1)
                ? A1 + (long)(bm + arow) * K1 + k0 + acol
                : A2 + (long)(bm + arow) * K2 + (k0 - K1) + acol;
            #pragma unroll
            for (int i = 0; i < 4; i++) aR[i] = *(const float4*)(ap + i * 4);
            const float* bp = Bm + (long)(k0 + bkk) * Ntot + bn + bcol;
            #pragma unroll
            for (int i = 0; i < 4; i++) bR[i] = *(const float4*)(bp + i * 32);
        }

        #pragma unroll 4
        for (int kk = 0; kk < 32; kk++) {
            ulonglong2 a01 = *(const ulonglong2*)&As[kk][r0];
            ulonglong2 a23 = *(const ulonglong2*)&As[kk][r0 + 4];
            u64 ap4[4] = { a01.x, a01.y, a23.x, a23.y };
            float4 b0 = *(const float4*)&Bs[kk][c0];
            float4 b1 = *(const float4*)&Bs[kk][c0 + 4];
            u64 bp8[8] = { pack2(b0.x), pack2(b0.y), pack2(b0.z), pack2(b0.w),
                           pack2(b1.x), pack2(b1.y), pack2(b1.z), pack2(b1.w) };
            #pragma unroll
            for (int i = 0; i < 4; i++)
                #pragma unroll
                for (int j = 0; j < 8; j++)
                    ffma2(acc[i][j], ap4[i], bp8[j]);
        }
    }

    // epilogue
    float* Cp = C + (long)blockIdx.z * partStride;
    float bv[8];
    #pragma unroll
    for (int j = 0; j < 8; j++) bv[j] = bias ? bias[bn + c0 + j] : 0.f;

    #pragma unroll
    for (int i = 0; i < 4; i++) {
        float lo[8], hi[8];
        #pragma unroll
        for (int j = 0; j < 8; j++) { unpack2(acc[i][j], lo[j], hi[j]); lo[j] += bv[j]; hi[j] += bv[j]; }
        long row0 = bm + r0 + 2 * i;
        float4* o0 = (float4*)(Cp + row0 * Ntot + bn + c0);
        float4* o1 = (float4*)(Cp + (row0 + 1) * Ntot + bn + c0);
        o0[0] = make_float4(lo[0], lo[1], lo[2], lo[3]);
        o0[1] = make_float4(lo[4], lo[5], lo[6], lo[7]);
        o1[0] = make_float4(hi[0], hi[1], hi[2], hi[3]);
        o1[1] = make_float4(hi[4], hi[5], hi[6], hi[7]);
    }
}

// ---------------- split-K combine + bias + residual + relu ----------------
__global__ void __launch_bounds__(256)
combine_layer(const float* __restrict__ bias,
              const float* __restrict__ xin,
              float* __restrict__ xout)
{
    const int i = blockIdx.x * 256 + threadIdx.x;      // over BSZ*DIM/4
    const float4* p = (const float4*)g_part;
    const int Q = BSZ * DIM / 4;
    float4 v0 = p[i], v1 = p[i + Q], v2 = p[i + 2 * Q], v3 = p[i + 3 * Q];
    float4 xi = ((const float4*)xin)[i];
    float4 bb = ((const float4*)bias)[i & 31];
    float4 o;
    o.x = fmaxf(v0.x + v1.x + v2.x + v3.x + xi.x + bb.x, 0.f);
    o.y = fmaxf(v0.y + v1.y + v2.y + v3.y + xi.y + bb.y, 0.f);
    o.z = fmaxf(v0.z + v1.z + v2.z + v3.z + xi.z + bb.z, 0.f);
    o.w = fmaxf(v0.w + v1.w + v2.w + v3.w + xi.w + bb.w, 0.f);
    ((float4*)xout)[i] = o;
}

// ---------------- attention (L=2, one warp per head) ----------------
__global__ void __launch_bounds__(128)
attn_kernel()
{
    const int b = blockIdx.x;
    const int h = threadIdx.x >> 5;
    const int d = threadIdx.x & 31;

    const float* p0 = g_qkv[0] + (long)b * NQKV + h * 32 + d;
    const float* p1 = g_qkv[1] + (long)b * NQKV + h * 32 + d;
    float q0 = p0[0], k0 = p0[128], v0 = p0[256];
    float q1 = p1[0], k1 = p1[128], v1 = p1[256];

    float s00 = q0 * k0, s01 = q0 * k1, s10 = q1 * k0, s11 = q1 * k1;
    #pragma unroll
    for (int o = 16; o; o >>= 1) {
        s00 += __shfl_xor_sync(0xffffffffu, s00, o);
        s01 += __shfl_xor_sync(0xffffffffu, s01, o);
        s10 += __shfl_xor_sync(0xffffffffu, s10, o);
        s11 += __shfl_xor_sync(0xffffffffu, s11, o);
    }
    const float inv = 0.17677669529663687f;  // 1/sqrt(32)
    s00 *= inv; s01 *= inv; s10 *= inv; s11 *= inv;

    float m0 = fmaxf(s00, s01), m1 = fmaxf(s10, s11);
    float e00 = expf(s00 - m0), e01 = expf(s01 - m0);
    float e10 = expf(s10 - m1), e11 = expf(s11 - m1);
    float o0 = (e00 * v0 + e01 * v1) / (e00 + e01);
    float o1 = (e10 * v0 + e11 * v1) / (e10 + e11);

    g_obar[(long)b * DIM + h * 32 + d] = 0.5f * (o0 + o1);
}

// ---------------- host launcher ----------------
extern "C" void kernel_launch(void* const* d_in, const int* in_sizes, int n_in,
                              void* d_out, int out_size)
{
    const int*   drug = (const int*)  d_in[0];
    const int*   adjE = (const int*)  d_in[1];
    const int*   adjR = (const int*)  d_in[2];
    const float* ew   = (const float*)d_in[3];
    const float* E    = (const float*)d_in[4];
    const float* Wrel = (const float*)d_in[5];
    const float* resW = (const float*)d_in[6];
    const float* resb = (const float*)d_in[7];
    const float* inW  = (const float*)d_in[8];
    const float* inB  = (const float*)d_in[9];
    const float* outW = (const float*)d_in[10];
    const float* outB = (const float*)d_in[11];

    float *agg, *xbuf, *qkv, *obar, *Wcat, *inT, *outT;
    cudaGetSymbolAddress((void**)&agg,  g_agg);
    cudaGetSymbolAddress((void**)&xbuf, g_x);
    cudaGetSymbolAddress((void**)&qkv,  g_qkv);
    cudaGetSymbolAddress((void**)&obar, g_obar);
    cudaGetSymbolAddress((void**)&Wcat, g_Wcat);
    cudaGetSymbolAddress((void**)&inT,  g_inT);
    cudaGetSymbolAddress((void**)&outT, g_outT);
    float* part; cudaGetSymbolAddress((void**)&part, g_part);

    float* x0 = xbuf;
    float* x1 = xbuf + BSZ * DIM;
    float* x2 = xbuf + 2 * BSZ * DIM;

    prep_kernel<<<2432, 256>>>(Wrel, resW, inW, outW);
    agg_kernel<<<BSZ, 128>>>(drug, adjE, adjR, ew, E);

    // layer 0: part = split-K(agg|x0 @ Wcat0); x1 = relu(sum + b0 + x0)
    gemm128<<<dim3(BSZ / 128, 1, NSPLIT), 256>>>(
        agg, KAGG, x0, DIM, Wcat, DIM, part, (long)BSZ * DIM, KCHUNK, nullptr);
    combine_layer<<<BSZ * DIM / 4 / 256, 256>>>(resb, x0, x1);

    // layer 1
    gemm128<<<dim3(BSZ / 128, 1, NSPLIT), 256>>>(
        agg, KAGG, x1, DIM, Wcat + KCAT * DIM, DIM, part, (long)BSZ * DIM, KCHUNK, nullptr);
    combine_layer<<<BSZ * DIM / 4 / 256, 256>>>(resb + DIM, x1, x2);

    // qkv for both layers in one GEMM: M = 8192 (x1,x2 contiguous)
    gemm128<<<dim3(2 * BSZ / 128, NQKV / 128, 1), 256>>>(
        x1, DIM, nullptr, 0, inT, NQKV, qkv, 0, DIM, inB);

    attn_kernel<<<BSZ, 128>>>();

    // out projection
    gemm128<<<dim3(BSZ / 128, 1, 1), 256>>>(
        obar, DIM, nullptr, 0, outT, DIM, (float*)d_out, 0, DIM, outB);
}

// round 4
// speedup vs baseline: 2.2646x; 1.6189x over previous
#include <cuda_runtime.h>
#include <cuda_bf16.h>
#include <math.h>
#include <stdint.h>

typedef unsigned long long u64;
typedef unsigned int u32;

// ---------------- problem constants ----------------
#define BSZ   4096
#define DIM   128
#define KNBR  64
#define NREL  16
#define KAGG  2048          // NREL * DIM
#define KCAT  2176          // KAGG + DIM
#define NQKV  384
#define NSPLIT 4
#define KCHUNK 544          // KCAT / NSPLIT -> 17 k-tiles of 32

// ---------------- device scratch ----------------
__device__ __nv_bfloat16 g_aggh[BSZ * KAGG];
__device__ __nv_bfloat16 g_aggl[BSZ * KAGG];
__device__ float         g_x   [3][BSZ * DIM];        // fp32 x0,x1 (residuals)
__device__ __nv_bfloat16 g_xh  [3 * BSZ * DIM];       // x0,x1,x2 hi
__device__ __nv_bfloat16 g_xl  [3 * BSZ * DIM];       // x0,x1,x2 lo
__device__ float         g_qkv [2 * BSZ * NQKV];
__device__ __nv_bfloat16 g_oh  [BSZ * DIM];
__device__ __nv_bfloat16 g_ol  [BSZ * DIM];
__device__ __nv_bfloat16 g_Wth [2 * DIM * KCAT];      // B for layer gemm, [l][e][k]
__device__ __nv_bfloat16 g_Wtl [2 * DIM * KCAT];
__device__ __nv_bfloat16 g_inh [NQKV * DIM];
__device__ __nv_bfloat16 g_inl [NQKV * DIM];
__device__ __nv_bfloat16 g_outh[DIM * DIM];
__device__ __nv_bfloat16 g_outl[DIM * DIM];
__device__ float         g_part[NSPLIT * BSZ * DIM];

// ================= PTX helpers =================
__device__ __forceinline__ u32 smem_u32(const void* p) {
    u32 a; asm("{ .reg .u64 t; cvta.to.shared.u64 t, %1; cvt.u32.u64 %0, t; }" : "=r"(a) : "l"(p));
    return a;
}
__device__ __forceinline__ void cp16(u32 s, const void* g) {
    asm volatile("cp.async.cg.shared.global [%0], [%1], 16;" :: "r"(s), "l"(g));
}
__device__ __forceinline__ void cp_commit() {
    asm volatile("cp.async.commit_group;" ::: "memory");
}
__device__ __forceinline__ void cp_wait_all() {
    asm volatile("cp.async.wait_group 0;" ::: "memory");
}
__device__ __forceinline__ void ldsm4(u32* r, u32 addr) {
    asm volatile("ldmatrix.sync.aligned.m8n8.x4.shared.b16 {%0,%1,%2,%3}, [%4];"
                 : "=r"(r[0]), "=r"(r[1]), "=r"(r[2]), "=r"(r[3]) : "r"(addr));
}
__device__ __forceinline__ void mma16816(float* c, const u32* a, const u32* b) {
    asm volatile(
        "mma.sync.aligned.m16n8k16.row.col.f32.bf16.bf16.f32 "
        "{%0,%1,%2,%3}, {%4,%5,%6,%7}, {%8,%9}, {%0,%1,%2,%3};"
        : "+f"(c[0]), "+f"(c[1]), "+f"(c[2]), "+f"(c[3])
        : "r"(a[0]), "r"(a[1]), "r"(a[2]), "r"(a[3]), "r"(b[0]), "r"(b[1]));
}
__device__ __forceinline__ void split_bf16(float v, __nv_bfloat16& h, __nv_bfloat16& l) {
    h = __float2bfloat16_rn(v);
    l = __float2bfloat16_rn(v - __bfloat162float(h));
}

// ================= prep kernels =================
// W_rel[l,r,d,e] -> B[l][e][r*128+d]  (bf16 hi/lo)
__global__ void transpose_wrel(const float* __restrict__ Wrel)
{
    __shared__ float tile[32][33];
    const int mat = blockIdx.z;           // l*16 + r
    const int l = mat >> 4, r = mat & 15;
    const int tx = threadIdx.x, ty = threadIdx.y;
    const float* src = Wrel + (long)mat * 16384;
    int e_in = blockIdx.x * 32 + tx;
    #pragma unroll
    for (int i = 0; i < 4; i++) {
        int d = blockIdx.y * 32 + ty + i * 8;
        tile[ty + i * 8][tx] = src[d * 128 + e_in];
    }
    __syncthreads();
    const long base = (long)l * (DIM * KCAT);
    #pragma unroll
    for (int i = 0; i < 4; i++) {
        int e = blockIdx.x * 32 + ty + i * 8;
        int d = blockIdx.y * 32 + tx;
        float v = tile[tx][ty + i * 8];
        __nv_bfloat16 h, lo; split_bf16(v, h, lo);
        long o = base + (long)e * KCAT + r * 128 + d;
        g_Wth[o] = h; g_Wtl[o] = lo;
    }
}

// res_W[l,e,d] -> B[l][e][2048+d]; plus inW / outW straight conversion
__global__ void prep_rest(const float* __restrict__ resW,
                          const float* __restrict__ inW,
                          const float* __restrict__ outW)
{
    int i = blockIdx.x * 256 + threadIdx.x;
    const int NR = 2 * DIM * DIM;         // 32768
    const int NI = NQKV * DIM;            // 49152
    const int NO = DIM * DIM;             // 16384
    if (i < NR) {
        int l = i >> 14, e = (i >> 7) & 127, d = i & 127;
        __nv_bfloat16 h, lo; split_bf16(resW[i], h, lo);
        long o = (long)l * (DIM * KCAT) + (long)e * KCAT + 2048 + d;
        g_Wth[o] = h; g_Wtl[o] = lo;
    } else if (i < NR + NI) {
        int t = i - NR;
        __nv_bfloat16 h, lo; split_bf16(inW[t], h, lo);
        g_inh[t] = h; g_inl[t] = lo;
    } else if (i < NR + NI + NO) {
        int t = i - NR - NI;
        __nv_bfloat16 h, lo; split_bf16(outW[t], h, lo);
        g_outh[t] = h; g_outl[t] = lo;
    }
}

// ---------------- agg: relation scatter + x0 gather (bf16 hi/lo outputs) ----
__global__ void __launch_bounds__(128)
agg_kernel(const int* __restrict__ drug,
           const int* __restrict__ adjE,
           const int* __restrict__ adjR,
           const float* __restrict__ ew,
           const float* __restrict__ E)
{
    __shared__ float s[NREL * DIM];
    __shared__ int   se[KNBR];
    __shared__ int   sr[KNBR];
    __shared__ float sw[KNBR];

    const int b = blockIdx.x;
    const int d = threadIdx.x;

    #pragma unroll
    for (int r = 0; r < NREL; r++) s[r * DIM + d] = 0.f;

    if (d < KNBR) {
        se[d] = adjE[b * KNBR + d];
        sr[d] = adjR[b * KNBR + d];
        sw[d] = ew  [b * KNBR + d];
    }
    {
        float v = E[(long)drug[b] * DIM + d];
        g_x[0][b * DIM + d] = v;
        __nv_bfloat16 h, lo; split_bf16(v, h, lo);
        g_xh[b * DIM + d] = h; g_xl[b * DIM + d] = lo;
    }
    __syncthreads();

    #pragma unroll 1
    for (int k = 0; k < KNBR; k += 4) {
        float e0 = E[(long)se[k + 0] * DIM + d];
        float e1 = E[(long)se[k + 1] * DIM + d];
        float e2 = E[(long)se[k + 2] * DIM + d];
        float e3 = E[(long)se[k + 3] * DIM + d];
        s[sr[k + 0] * DIM + d] += sw[k + 0] * e0;
        s[sr[k + 1] * DIM + d] += sw[k + 1] * e1;
        s[sr[k + 2] * DIM + d] += sw[k + 2] * e2;
        s[sr[k + 3] * DIM + d] += sw[k + 3] * e3;
    }
    const long ao = (long)b * KAGG;
    #pragma unroll
    for (int r = 0; r < NREL; r++) {
        float v = s[r * DIM + d];
        __nv_bfloat16 h, lo; split_bf16(v, h, lo);
        g_aggh[ao + r * DIM + d] = h;
        g_aggl[ao + r * DIM + d] = lo;
    }
}

// ================= bf16 hi/lo 3-pass tensor-core GEMM =================
// C[m,n] = sum_k A[m,k]*B[n,k]; A = [A1 | A2] (K1 + K2 cols), bf16 hi/lo pairs.
// k range per CTA.z: [z*kchunk, z*kchunk + ntiles*32).
// SMEM: 2 stages x { Ah, Al, Bh, Bl } each 128 rows x 80B (32 bf16 + pad)
#define ROWB   80
#define REGB   10240            // 128 * 80
#define STAGEB 40960
#define GT_SMEM (2 * STAGEB)

__global__ void __launch_bounds__(256, 1)
gemm_bf16(const __nv_bfloat16* __restrict__ A1h, const __nv_bfloat16* __restrict__ A1l, int K1,
          const __nv_bfloat16* __restrict__ A2h, const __nv_bfloat16* __restrict__ A2l, int K2,
          const __nv_bfloat16* __restrict__ Bh,  const __nv_bfloat16* __restrict__ Bl,  int KB,
          float* __restrict__ C, int ldC, long partStride,
          int kchunk, int ntiles, const float* __restrict__ bias)
{
    extern __shared__ __align__(128) char smem[];
    const u32 sb  = smem_u32(smem);
    const int tid = threadIdx.x, lane = tid & 31, wid = tid >> 5;
    const int bm  = blockIdx.x * 128;
    const int bn  = blockIdx.y * 128;
    const int kbeg = blockIdx.z * kchunk;

    // producer mapping: thread -> (row, 16-elem segment)
    const int prow = tid >> 1, pseg = tid & 1;
    const u32 pdst = (u32)(prow * ROWB + pseg * 32);

    auto issue = [&](int t, int s) {
        const int k0 = kbeg + t * 32;
        const __nv_bfloat16 *pAh, *pAl;
        if (k0 < K1) {
            long o = (long)(bm + prow) * K1 + k0 + pseg * 16;
            pAh = A1h + o; pAl = A1l + o;
        } else {
            long o = (long)(bm + prow) * K2 + (k0 - K1) + pseg * 16;
            pAh = A2h + o; pAl = A2l + o;
        }
        long ob = (long)(bn + prow) * KB + k0 + pseg * 16;
        u32 d = sb + s * STAGEB + pdst;
        cp16(d,                 pAh);     cp16(d + 16,             pAh + 8);
        cp16(d + REGB,          pAl);     cp16(d + REGB + 16,      pAl + 8);
        cp16(d + 2 * REGB,      Bh + ob); cp16(d + 2 * REGB + 16,  Bh + ob + 8);
        cp16(d + 3 * REGB,      Bl + ob); cp16(d + 3 * REGB + 16,  Bl + ob + 8);
    };

    // consumer mapping: 8 warps -> 4 (m) x 2 (n); warp tile 32x64
    const int wr = wid & 3, wc = wid >> 2;
    const u32 a_off = (u32)((wr * 32 + (lane & 15)) * ROWB + (lane >> 4) * 16);
    const u32 b_off = (u32)(2 * REGB +
                            (wc * 64 + (lane & 7) + ((lane >> 4) & 1) * 8) * ROWB +
                            ((lane >> 3) & 1) * 16);

    float acc[2][8][4];
    #pragma unroll
    for (int i = 0; i < 2; i++)
        #pragma unroll
        for (int j = 0; j < 8; j++)
            #pragma unroll
            for (int q = 0; q < 4; q++) acc[i][j][q] = 0.f;

    issue(0, 0);
    cp_commit();

    for (int t = 0; t < ntiles; t++) {
        const int s = t & 1;
        cp_wait_all();
        __syncthreads();
        if (t + 1 < ntiles) { issue(t + 1, 1 - s); cp_commit(); }

        const u32 base = sb + s * STAGEB;
        #pragma unroll
        for (int kk = 0; kk < 32; kk += 16) {
            u32 ah[2][4], al[2][4], bh[4][4], bl[4][4];
            #pragma unroll
            for (int mi = 0; mi < 2; mi++) {
                ldsm4(ah[mi], base + a_off + mi * (16 * ROWB) + kk * 2);
                ldsm4(al[mi], base + REGB + a_off + mi * (16 * ROWB) + kk * 2);
            }
            #pragma unroll
            for (int nj = 0; nj < 4; nj++) {
                ldsm4(bh[nj], base + b_off + nj * (16 * ROWB) + kk * 2);
                ldsm4(bl[nj], base + REGB + b_off + nj * (16 * ROWB) + kk * 2);
            }
            #pragma unroll
            for (int mi = 0; mi < 2; mi++)
                #pragma unroll
                for (int nt = 0; nt < 8; nt++) {
                    const u32* pbh = &bh[nt >> 1][(nt & 1) * 2];
                    const u32* pbl = &bl[nt >> 1][(nt & 1) * 2];
                    mma16816(acc[mi][nt], ah[mi], pbh);
                    mma16816(acc[mi][nt], ah[mi], pbl);
                    mma16816(acc[mi][nt], al[mi], pbh);
                }
        }
        __syncthreads();
    }

    // epilogue
    float* Cp = C + (long)blockIdx.z * partStride;
    const int gr  = bm + wr * 32 + (lane >> 2);
    const int gcb = bn + wc * 64 + (lane & 3) * 2;
    #pragma unroll
    for (int mi = 0; mi < 2; mi++)
        #pragma unroll
        for (int nt = 0; nt < 8; nt++) {
            int r0 = gr + mi * 16;
            int c  = gcb + nt * 8;
            float b0 = 0.f, b1 = 0.f;
            if (bias) { b0 = bias[c]; b1 = bias[c + 1]; }
            float2 v0 = make_float2(acc[mi][nt][0] + b0, acc[mi][nt][1] + b1);
            float2 v1 = make_float2(acc[mi][nt][2] + b0, acc[mi][nt][3] + b1);
            *(float2*)(Cp + (long)r0 * ldC + c)       = v0;
            *(float2*)(Cp + (long)(r0 + 8) * ldC + c) = v1;
        }
}

// ---------------- split-K combine + bias + residual + relu ----------------
__global__ void __launch_bounds__(256)
combine_layer(const float* __restrict__ bias,
              const float* __restrict__ xin,
              float* __restrict__ xout,
              __nv_bfloat16* __restrict__ xh,
              __nv_bfloat16* __restrict__ xl)
{
    const int i = blockIdx.x * 256 + threadIdx.x;      // over BSZ*DIM/4
    const float4* p = (const float4*)g_part;
    const int Q = BSZ * DIM / 4;
    float4 v0 = p[i], v1 = p[i + Q], v2 = p[i + 2 * Q], v3 = p[i + 3 * Q];
    float4 xi = ((const float4*)xin)[i];
    float4 bb = ((const float4*)bias)[i & 31];
    float4 o;
    o.x = fmaxf(v0.x + v1.x + v2.x + v3.x + xi.x + bb.x, 0.f);
    o.y = fmaxf(v0.y + v1.y + v2.y + v3.y + xi.y + bb.y, 0.f);
    o.z = fmaxf(v0.z + v1.z + v2.z + v3.z + xi.z + bb.z, 0.f);
    o.w = fmaxf(v0.w + v1.w + v2.w + v3.w + xi.w + bb.w, 0.f);
    ((float4*)xout)[i] = o;

    __nv_bfloat16 hx, lx, hy, ly, hz, lz, hw, lw;
    split_bf16(o.x, hx, lx); split_bf16(o.y, hy, ly);
    split_bf16(o.z, hz, lz); split_bf16(o.w, hw, lw);
    __nv_bfloat162* ph = (__nv_bfloat162*)xh;
    __nv_bfloat162* pl = (__nv_bfloat162*)xl;
    ph[2 * i]     = __nv_bfloat162(hx, hy);
    ph[2 * i + 1] = __nv_bfloat162(hz, hw);
    pl[2 * i]     = __nv_bfloat162(lx, ly);
    pl[2 * i + 1] = __nv_bfloat162(lz, lw);
}

// ---------------- attention (L=2, one warp per head) ----------------
__global__ void __launch_bounds__(128)
attn_kernel()
{
    const int b = blockIdx.x;
    const int h = threadIdx.x >> 5;
    const int d = threadIdx.x & 31;

    const float* p0 = g_qkv + (long)b * NQKV + h * 32 + d;
    const float* p1 = p0 + (long)BSZ * NQKV;
    float q0 = p0[0], k0 = p0[128], v0 = p0[256];
    float q1 = p1[0], k1 = p1[128], v1 = p1[256];

    float s00 = q0 * k0, s01 = q0 * k1, s10 = q1 * k0, s11 = q1 * k1;
    #pragma unroll
    for (int o = 16; o; o >>= 1) {
        s00 += __shfl_xor_sync(0xffffffffu, s00, o);
        s01 += __shfl_xor_sync(0xffffffffu, s01, o);
        s10 += __shfl_xor_sync(0xffffffffu, s10, o);
        s11 += __shfl_xor_sync(0xffffffffu, s11, o);
    }
    const float inv = 0.17677669529663687f;  // 1/sqrt(32)
    s00 *= inv; s01 *= inv; s10 *= inv; s11 *= inv;

    float m0 = fmaxf(s00, s01), m1 = fmaxf(s10, s11);
    float e00 = expf(s00 - m0), e01 = expf(s01 - m0);
    float e10 = expf(s10 - m1), e11 = expf(s11 - m1);
    float o0 = (e00 * v0 + e01 * v1) / (e00 + e01);
    float o1 = (e10 * v0 + e11 * v1) / (e10 + e11);

    float v = 0.5f * (o0 + o1);
    __nv_bfloat16 hh, ll; split_bf16(v, hh, ll);
    g_oh[(long)b * DIM + h * 32 + d] = hh;
    g_ol[(long)b * DIM + h * 32 + d] = ll;
}

// ---------------- host launcher ----------------
extern "C" void kernel_launch(void* const* d_in, const int* in_sizes, int n_in,
                              void* d_out, int out_size)
{
    const int*   drug = (const int*)  d_in[0];
    const int*   adjE = (const int*)  d_in[1];
    const int*   adjR = (const int*)  d_in[2];
    const float* ew   = (const float*)d_in[3];
    const float* E    = (const float*)d_in[4];
    const float* Wrel = (const float*)d_in[5];
    const float* resW = (const float*)d_in[6];
    const float* resb = (const float*)d_in[7];
    const float* inW  = (const float*)d_in[8];
    const float* inB  = (const float*)d_in[9];
    const float* outW = (const float*)d_in[10];
    const float* outB = (const float*)d_in[11];

    __nv_bfloat16 *aggh, *aggl, *xh, *xl, *oh, *ol, *Wth, *Wtl, *inh, *inl, *outh, *outl;
    float *xf, *qkv, *part;
    cudaGetSymbolAddress((void**)&aggh, g_aggh);
    cudaGetSymbolAddress((void**)&aggl, g_aggl);
    cudaGetSymbolAddress((void**)&xf,   g_x);
    cudaGetSymbolAddress((void**)&xh,   g_xh);
    cudaGetSymbolAddress((void**)&xl,   g_xl);
    cudaGetSymbolAddress((void**)&qkv,  g_qkv);
    cudaGetSymbolAddress((void**)&oh,   g_oh);
    cudaGetSymbolAddress((void**)&ol,   g_ol);
    cudaGetSymbolAddress((void**)&Wth,  g_Wth);
    cudaGetSymbolAddress((void**)&Wtl,  g_Wtl);
    cudaGetSymbolAddress((void**)&inh,  g_inh);
    cudaGetSymbolAddress((void**)&inl,  g_inl);
    cudaGetSymbolAddress((void**)&outh, g_outh);
    cudaGetSymbolAddress((void**)&outl, g_outl);
    cudaGetSymbolAddress((void**)&part, g_part);

    cudaFuncSetAttribute(gemm_bf16, cudaFuncAttributeMaxDynamicSharedMemorySize, GT_SMEM);

    transpose_wrel<<<dim3(4, 4, 32), dim3(32, 8)>>>(Wrel);
    prep_rest<<<(2 * DIM * DIM + NQKV * DIM + DIM * DIM + 255) / 256, 256>>>(resW, inW, outW);
    agg_kernel<<<BSZ, 128>>>(drug, adjE, adjR, ew, E);

    // layer 0: part = split-K((agg|x0) @ Wcat0^T); x1 = relu(sum + b0 + x0)
    gemm_bf16<<<dim3(BSZ / 128, 1, NSPLIT), 256, GT_SMEM>>>(
        aggh, aggl, KAGG, xh, xl, DIM, Wth, Wtl, KCAT,
        part, DIM, (long)BSZ * DIM, KCHUNK, KCHUNK / 32, nullptr);
    combine_layer<<<BSZ * DIM / 4 / 256, 256>>>(
        resb, xf, xf + BSZ * DIM, xh + BSZ * DIM, xl + BSZ * DIM);

    // layer 1
    gemm_bf16<<<dim3(BSZ / 128, 1, NSPLIT), 256, GT_SMEM>>>(
        aggh, aggl, KAGG, xh + BSZ * DIM, xl + BSZ * DIM, DIM,
        Wth + DIM * KCAT, Wtl + DIM * KCAT, KCAT,
        part, DIM, (long)BSZ * DIM, KCHUNK, KCHUNK / 32, nullptr);
    combine_layer<<<BSZ * DIM / 4 / 256, 256>>>(
        resb + DIM, xf + BSZ * DIM, xf + 2 * BSZ * DIM,
        xh + 2 * BSZ * DIM, xl + 2 * BSZ * DIM);

    // qkv for both layer outputs: M=8192 (x1,x2 contiguous), N=384, K=128
    gemm_bf16<<<dim3(2 * BSZ / 128, NQKV / 128, 1), 256, GT_SMEM>>>(
        xh + BSZ * DIM, xl + BSZ * DIM, DIM, nullptr, nullptr, 0,
        inh, inl, DIM, qkv, NQKV, 0, DIM, DIM / 32, inB);

    attn_kernel<<<BSZ, 128>>>();

    // out projection: M=4096, N=128, K=128 -> d_out
    gemm_bf16<<<dim3(BSZ / 128, 1, 1), 256, GT_SMEM>>>(
        oh, ol, DIM, nullptr, nullptr, 0,
        outh, outl, DIM, (float*)d_out, DIM, 0, DIM, DIM / 32, outB);
}